// round 16
// baseline (speedup 1.0000x reference)
#include <cuda_runtime.h>
#include <cuda_bf16.h>
#include <cstdint>

// ---------------------------------------------------------------------------
// NeuralCA: 40 steps of  x = clip(x + MLP(conv3x3(x)), 0, 1)
// R16: w2 (52% of FLOPs) on the tensor pipe via baseline-PTX warp mma.sync
// m16n8k16 bf16 (compute_103-legal; tcgen05 is sm_103a-only and the harness
// lowers through compute_103). 4-pass hi/lo split-bf16 => ~fp32 accuracy.
// conv + w1 keep the proven fp32 FFMA2 path. Epilogue: in-register D,
// +b2, relu, fp32 w3, quad shfl-reduce (no cross-warp SMEM reduction).
// ---------------------------------------------------------------------------

#define BV     4
#define CHN    16
#define HH     224
#define WW     224
#define HWSZ   (HH * WW)
#define NSTEPS 40
#define NPIX   (BV * HWSZ)            // 200704
#define NTHR   256
#define PIXPB  128
#define NBLK   (NPIX / PIXPB)         // 1568

typedef unsigned long long ull;

// ---- fp32 packed-weight layout (ull slots) ---------------------------------
#define OFF_WP 0
#define OFF_W1 3456
#define OFF_W3 6528                   // w3: [h2ch n][dx_pair(8)]
#define OFF_B1 7552
#define OFF_B2 7616
#define NPACK  7680                   // ull = 61440 B

// ---- SMEM map (ull units) --------------------------------------------------
#define XCH_P   NPACK                 // p:  [24 pair-rows][128 pix]
#define XCH_H1  (XCH_P + 24 * PIXPB)  // h1: [64 pair-rows][128 pix]  (f32 pairs)
#define BFR_HI  (XCH_H1 + 64 * PIXPB) // w2 B-frags hi: 4096 uint2 = 4096 ull
#define BFR_LO  (BFR_HI + 4096)
#define SMEM_ULL (BFR_LO + 4096)      // 27136 ull
#define SMEM_BYTES (SMEM_ULL * 8)     // 217088 B

__device__ __align__(16) float2 g_packed[NPACK];
__device__ __align__(16) uint2 g_w2frag_hi[4096];   // [nt(16)][kc(8)][lane(32)]
__device__ __align__(16) uint2 g_w2frag_lo[4096];
__device__ float g_buf0[BV * CHN * HWSZ];
__device__ float g_buf1[BV * CHN * HWSZ];

// ---- packed f32x2 helpers --------------------------------------------------
__device__ __forceinline__ ull pk2(float a, float b) {
    ull r;
    asm("mov.b64 %0, {%1, %2};" : "=l"(r)
        : "r"(__float_as_uint(a)), "r"(__float_as_uint(b)));
    return r;
}
__device__ __forceinline__ void upk2(ull v, float& a, float& b) {
    unsigned int lo, hi;
    asm("mov.b64 {%0, %1}, %2;" : "=r"(lo), "=r"(hi) : "l"(v));
    a = __uint_as_float(lo);
    b = __uint_as_float(hi);
}
__device__ __forceinline__ ull f2fma(ull a, ull b, ull c) {
    ull d;
    asm("fma.rn.f32x2 %0, %1, %2, %3;" : "=l"(d) : "l"(a), "l"(b), "l"(c));
    return d;
}
__device__ __forceinline__ ull f2add(ull a, ull b) {
    ull d;
    asm("add.rn.f32x2 %0, %1, %2;" : "=l"(d) : "l"(a), "l"(b));
    return d;
}
__device__ __forceinline__ ull f2relu(ull a) {
    float x, y;
    upk2(a, x, y);
    return pk2(fmaxf(x, 0.0f), fmaxf(y, 0.0f));
}
__device__ __forceinline__ uint32_t bf2_bits(float lo, float hi) {
    __nv_bfloat162 h = __floats2bfloat162_rn(lo, hi);   // lo -> .x (low half)
    return *reinterpret_cast<uint32_t*>(&h);
}

// ---- warp mma.sync m16n8k16 bf16 -------------------------------------------
__device__ __forceinline__ void mma_bf16(float* d, const uint32_t* a, uint2 b) {
    asm volatile(
        "mma.sync.aligned.m16n8k16.row.col.f32.bf16.bf16.f32 "
        "{%0,%1,%2,%3}, {%4,%5,%6,%7}, {%8,%9}, {%0,%1,%2,%3};"
        : "+f"(d[0]), "+f"(d[1]), "+f"(d[2]), "+f"(d[3])
        : "r"(a[0]), "r"(a[1]), "r"(a[2]), "r"(a[3]), "r"(b.x), "r"(b.y));
}

// ---- pack kernels (tiny, once per launch) ----------------------------------
__global__ void nca_pack(const float* __restrict__ wp, const float* __restrict__ w1,
                         const float* __restrict__ b1,
                         const float* __restrict__ b2, const float* __restrict__ w3) {
    int i = blockIdx.x * blockDim.x + threadIdx.x;
    if (i >= NPACK) return;
    float lo, hi;
    if (i < OFF_W1) {                       // conv (OIHW, O=48,I=16,3x3)
        int oc2 = i % 24;
        int r   = i / 24;
        int ic  = r / 9;
        int t   = r % 9;
        lo = wp[((2 * oc2) * 16 + ic) * 9 + t];
        hi = wp[((2 * oc2 + 1) * 16 + ic) * 9 + t];
    } else if (i < OFF_W3) {                // w1 [128,48] -> [c][o_pair]
        int j  = i - OFF_W1;
        int o2 = j % 64;
        int c  = j / 64;
        lo = w1[(2 * o2) * 48 + c];
        hi = w1[(2 * o2 + 1) * 48 + c];
    } else if (i < OFF_B1) {                // w3 [16,128] -> [h2ch][dx_pair]
        int j  = i - OFF_W3;
        int k2 = j % 8;
        int o  = j / 8;
        lo = w3[(2 * k2) * 128 + o];
        hi = w3[(2 * k2 + 1) * 128 + o];
    } else if (i < OFF_B2) {                // b1
        int j = i - OFF_B1;
        lo = b1[2 * j];
        hi = b1[2 * j + 1];
    } else {                                // b2
        int j = i - OFF_B2;
        lo = b2[2 * j];
        hi = b2[2 * j + 1];
    }
    g_packed[i] = make_float2(lo, hi);
}

__global__ void nca_pack_w2frag(const float* __restrict__ w2) {
    int i = blockIdx.x * blockDim.x + threadIdx.x;   // [nt*8 + kc]*32 + lane
    if (i >= 4096) return;
    int lane = i & 31;
    int kc   = (i >> 5) & 7;
    int nt   = i >> 8;
    int n    = nt * 8 + (lane >> 2);
    int c    = lane & 3;
    int k0   = kc * 16 + 2 * c;
    const float* row = w2 + n * 128;
    float v0 = row[k0],     v1 = row[k0 + 1];
    float v2 = row[k0 + 8], v3 = row[k0 + 9];
    // hi parts
    __nv_bfloat162 h0 = __floats2bfloat162_rn(v0, v1);
    __nv_bfloat162 h1 = __floats2bfloat162_rn(v2, v3);
    // lo residuals
    float r0 = v0 - __bfloat162float(h0.x), r1 = v1 - __bfloat162float(h0.y);
    float r2 = v2 - __bfloat162float(h1.x), r3 = v3 - __bfloat162float(h1.y);
    __nv_bfloat162 l0 = __floats2bfloat162_rn(r0, r1);
    __nv_bfloat162 l1 = __floats2bfloat162_rn(r2, r3);
    g_w2frag_hi[i] = make_uint2(*reinterpret_cast<uint32_t*>(&h0),
                                *reinterpret_cast<uint32_t*>(&h1));
    g_w2frag_lo[i] = make_uint2(*reinterpret_cast<uint32_t*>(&l0),
                                *reinterpret_cast<uint32_t*>(&l1));
}

// ---- fused CA step ----------------------------------------------------------
// src_sel: 0=external input, 1=g_buf0, 2=g_buf1
// dst_sel: 1=g_buf0, 2=g_buf1, 3=external output
__global__ __launch_bounds__(NTHR, 1)
void nca_step(const float* __restrict__ src_ext, float* __restrict__ dst_ext,
              int src_sel, int dst_sel) {
    extern __shared__ ull sw[];
    const float* swf = (const float*)sw;

    int tid = threadIdx.x;
    int e   = tid >> 5;           // warp id
    int s   = tid & 31;           // lane

    // stage fp32 packed weights + w2 B-fragments
    {
        const float4* gp = (const float4*)g_packed;
        float4*       sp = (float4*)sw;
        for (int i = tid; i < NPACK / 2; i += NTHR) sp[i] = gp[i];
        const float4* gh = (const float4*)g_w2frag_hi;
        const float4* gl = (const float4*)g_w2frag_lo;
        float4* bh = (float4*)(sw + BFR_HI);
        float4* bl = (float4*)(sw + BFR_LO);
        for (int i = tid; i < 2048; i += NTHR) { bh[i] = gh[i]; bl[i] = gl[i]; }
    }
    __syncthreads();

    const ull* wp2 = sw + OFF_WP;
    const ull* w1p = sw + OFF_W1;
    const ull* w3p = sw + OFF_W3;

    const float* src = (src_sel == 0) ? src_ext : ((src_sel == 1) ? g_buf0 : g_buf1);
    float*       dst = (dst_sel == 3) ? dst_ext : ((dst_sel == 1) ? g_buf0 : g_buf1);

    // 4 pixels/thread for conv/w1 phases: pixels s + 32k
    int py[4], px[4];
    const float* pxb[4];
    #pragma unroll
    for (int k = 0; k < 4; k++) {
        int idx = blockIdx.x * PIXPB + s + 32 * k;
        int b   = idx / HWSZ;
        int rm  = idx - b * HWSZ;
        py[k]   = rm / WW;
        px[k]   = rm - py[k] * WW;
        pxb[k]  = src + b * CHN * HWSZ;
    }

    // ---- 3x3 perception conv: my 6 p-ch = 3 pairs x 4 pix ----
    {
        ull p2[12];
        #pragma unroll
        for (int i = 0; i < 12; i++) p2[i] = 0ull;

        #pragma unroll 2
        for (int ic = 0; ic < CHN; ic++) {
            #pragma unroll
            for (int t = 0; t < 9; t++) {
                int dy = t / 3 - 1, dxo = t % 3 - 1;
                float v[4];
                #pragma unroll
                for (int k = 0; k < 4; k++) {
                    int yy = py[k] + dy, xx = px[k] + dxo;
                    bool ok = ((unsigned)yy < HH) && ((unsigned)xx < WW);
                    v[k] = ok ? __ldg(pxb[k] + ic * HWSZ + yy * WW + xx) : 0.0f;
                }
                ull w0 = wp2[(ic * 9 + t) * 24 + 3 * e + 0];
                ull w1v = wp2[(ic * 9 + t) * 24 + 3 * e + 1];
                ull w2v = wp2[(ic * 9 + t) * 24 + 3 * e + 2];
                #pragma unroll
                for (int k = 0; k < 4; k++) {
                    ull vv = pk2(v[k], v[k]);
                    p2[0 + k] = f2fma(w0,  vv, p2[0 + k]);
                    p2[4 + k] = f2fma(w1v, vv, p2[4 + k]);
                    p2[8 + k] = f2fma(w2v, vv, p2[8 + k]);
                }
            }
        }
        #pragma unroll
        for (int j = 0; j < 3; j++)
            #pragma unroll
            for (int k = 0; k < 4; k++)
                sw[XCH_P + (3 * e + j) * PIXPB + s + 32 * k] = p2[j * 4 + k];
    }
    __syncthreads();

    // ---- h1 = relu(W1 p + b1): my 8 pairs x 4 pix -> SMEM f32 pairs ----
    {
        ull h1[32];
        #pragma unroll
        for (int j = 0; j < 8; j++) {
            ull bj = sw[OFF_B1 + 8 * e + j];
            #pragma unroll
            for (int k = 0; k < 4; k++) h1[j * 4 + k] = bj;
        }
        #pragma unroll 4
        for (int c2 = 0; c2 < 24; c2++) {
            float fa[4], fb[4];
            #pragma unroll
            for (int k = 0; k < 4; k++) {
                int base = 2 * (XCH_P + c2 * PIXPB + s + 32 * k);
                fa[k] = swf[base];
                fb[k] = swf[base + 1];
            }
            {
                const ulonglong2* W = (const ulonglong2*)(w1p + (2 * c2) * 64 + 8 * e);
                ulonglong2 t0 = W[0], t1 = W[1], t2 = W[2], t3 = W[3];
                #pragma unroll
                for (int k = 0; k < 4; k++) {
                    ull ua = pk2(fa[k], fa[k]);
                    h1[0  + k] = f2fma(t0.x, ua, h1[0  + k]);
                    h1[4  + k] = f2fma(t0.y, ua, h1[4  + k]);
                    h1[8  + k] = f2fma(t1.x, ua, h1[8  + k]);
                    h1[12 + k] = f2fma(t1.y, ua, h1[12 + k]);
                    h1[16 + k] = f2fma(t2.x, ua, h1[16 + k]);
                    h1[20 + k] = f2fma(t2.y, ua, h1[20 + k]);
                    h1[24 + k] = f2fma(t3.x, ua, h1[24 + k]);
                    h1[28 + k] = f2fma(t3.y, ua, h1[28 + k]);
                }
            }
            {
                const ulonglong2* W = (const ulonglong2*)(w1p + (2 * c2 + 1) * 64 + 8 * e);
                ulonglong2 t0 = W[0], t1 = W[1], t2 = W[2], t3 = W[3];
                #pragma unroll
                for (int k = 0; k < 4; k++) {
                    ull ub = pk2(fb[k], fb[k]);
                    h1[0  + k] = f2fma(t0.x, ub, h1[0  + k]);
                    h1[4  + k] = f2fma(t0.y, ub, h1[4  + k]);
                    h1[8  + k] = f2fma(t1.x, ub, h1[8  + k]);
                    h1[12 + k] = f2fma(t1.y, ub, h1[12 + k]);
                    h1[16 + k] = f2fma(t2.x, ub, h1[16 + k]);
                    h1[20 + k] = f2fma(t2.y, ub, h1[20 + k]);
                    h1[24 + k] = f2fma(t3.x, ub, h1[24 + k]);
                    h1[28 + k] = f2fma(t3.y, ub, h1[28 + k]);
                }
            }
        }
        #pragma unroll
        for (int j = 0; j < 8; j++)
            #pragma unroll
            for (int k = 0; k < 4; k++)
                sw[XCH_H1 + (8 * e + j) * PIXPB + s + 32 * k] = f2relu(h1[j * 4 + k]);
    }
    __syncthreads();

    // ---- w2 via mma.sync bf16 (4-pass split): warp e owns pixels e*16..+15 --
    int r = s >> 2;                 // 0..7  (D rows r, r+8)
    int c = s & 3;                  // 0..3

    float d[64];
    #pragma unroll
    for (int i = 0; i < 64; i++) d[i] = 0.0f;

    int arow = e * 16 + r;          // CTA pixel of D row r
    #pragma unroll 1
    for (int kc = 0; kc < 8; kc++) {
        // A fragments from h1 (f32 pairs) -> bf16 hi/lo
        uint32_t ah[4], al[4];
        #pragma unroll
        for (int j = 0; j < 4; j++) {
            int c2  = kc * 8 + c + (j >> 1) * 4;        // j=0,1: k0..; j=2,3: k0+8
            int row = arow + (j & 1) * 8;               // j even: r, odd: r+8
            float f0, f1;
            upk2(sw[XCH_H1 + c2 * PIXPB + row], f0, f1);
            ah[j] = bf2_bits(f0, f1);
            __nv_bfloat162 hb = *reinterpret_cast<__nv_bfloat162*>(&ah[j]);
            al[j] = bf2_bits(f0 - __bfloat162float(hb.x),
                             f1 - __bfloat162float(hb.y));
        }
        const uint2* BH = (const uint2*)(sw + BFR_HI) + kc * 32 + s;
        const uint2* BL = (const uint2*)(sw + BFR_LO) + kc * 32 + s;
        #pragma unroll
        for (int nt = 0; nt < 16; nt++) mma_bf16(d + nt * 4, ah, BH[nt * 256]);
        #pragma unroll
        for (int nt = 0; nt < 16; nt++) mma_bf16(d + nt * 4, ah, BL[nt * 256]);
        #pragma unroll
        for (int nt = 0; nt < 16; nt++) mma_bf16(d + nt * 4, al, BH[nt * 256]);
        #pragma unroll
        for (int nt = 0; nt < 16; nt++) mma_bf16(d + nt * 4, al, BL[nt * 256]);
    }

    // ---- epilogue: h2 = relu(D + b2); dx = W3 h2; quad-reduce; store -------
    ull dx0[8], dx1[8];
    #pragma unroll
    for (int m = 0; m < 8; m++) { dx0[m] = 0ull; dx1[m] = 0ull; }

    #pragma unroll
    for (int nt = 0; nt < 16; nt++) {
        float ba, bb;
        upk2(sw[OFF_B2 + nt * 4 + c], ba, bb);
        float h00 = fmaxf(d[nt * 4 + 0] + ba, 0.0f);
        float h01 = fmaxf(d[nt * 4 + 1] + bb, 0.0f);
        float h10 = fmaxf(d[nt * 4 + 2] + ba, 0.0f);
        float h11 = fmaxf(d[nt * 4 + 3] + bb, 0.0f);
        int n0 = nt * 8 + 2 * c;
        const ulonglong2* Wa = (const ulonglong2*)(w3p + n0 * 8);
        ull wa[8], wb[8];
        #pragma unroll
        for (int m = 0; m < 4; m++) { ulonglong2 t2 = Wa[m];     wa[2*m] = t2.x; wa[2*m+1] = t2.y; }
        #pragma unroll
        for (int m = 0; m < 4; m++) { ulonglong2 t2 = Wa[m + 4]; wb[2*m] = t2.x; wb[2*m+1] = t2.y; }
        ull H00 = pk2(h00, h00), H01 = pk2(h01, h01);
        ull H10 = pk2(h10, h10), H11 = pk2(h11, h11);
        #pragma unroll
        for (int m = 0; m < 8; m++) dx0[m] = f2fma(wa[m], H00, dx0[m]);
        #pragma unroll
        for (int m = 0; m < 8; m++) dx0[m] = f2fma(wb[m], H01, dx0[m]);
        #pragma unroll
        for (int m = 0; m < 8; m++) dx1[m] = f2fma(wa[m], H10, dx1[m]);
        #pragma unroll
        for (int m = 0; m < 8; m++) dx1[m] = f2fma(wb[m], H11, dx1[m]);
    }
    // quad (lanes 4r..4r+3) hold disjoint n-contributions -> butterfly reduce
    #pragma unroll
    for (int m = 0; m < 8; m++) {
        dx0[m] = f2add(dx0[m], __shfl_xor_sync(0xffffffffu, dx0[m], 1));
        dx0[m] = f2add(dx0[m], __shfl_xor_sync(0xffffffffu, dx0[m], 2));
        dx1[m] = f2add(dx1[m], __shfl_xor_sync(0xffffffffu, dx1[m], 1));
        dx1[m] = f2add(dx1[m], __shfl_xor_sync(0xffffffffu, dx1[m], 2));
    }

    // lane c stores dx pairs {2c, 2c+1} for pixels arow and arow+8
    #pragma unroll
    for (int pv = 0; pv < 2; pv++) {
        int gidx = blockIdx.x * PIXPB + arow + 8 * pv;
        int b2i  = gidx / HWSZ;
        int rr   = gidx - b2i * HWSZ;
        const float* xbb = src + b2i * CHN * HWSZ;
        float*       dbb = dst + b2i * CHN * HWSZ;
        const ull* dxp = pv ? dx1 : dx0;
        #pragma unroll
        for (int t = 0; t < 2; t++) {
            int m = 2 * c + t;
            float d0, d1;
            upk2(dxp[m], d0, d1);
            int c0 = 2 * m;
            float x0 = __ldg(xbb + c0 * HWSZ + rr);
            float x1 = __ldg(xbb + (c0 + 1) * HWSZ + rr);
            dbb[c0 * HWSZ + rr]       = fminf(fmaxf(x0 + d0, 0.0f), 1.0f);
            dbb[(c0 + 1) * HWSZ + rr] = fminf(fmaxf(x1 + d1, 0.0f), 1.0f);
        }
    }
}

// ---------------------------------------------------------------------------
extern "C" void kernel_launch(void* const* d_in, const int* in_sizes, int n_in,
                              void* d_out, int out_size) {
    const float* x  = (const float*)d_in[0];
    const float* wp = (const float*)d_in[1];
    const float* w1 = (const float*)d_in[2];
    const float* b1 = (const float*)d_in[3];
    const float* w2 = (const float*)d_in[4];
    const float* b2 = (const float*)d_in[5];
    const float* w3 = (const float*)d_in[6];
    float* out = (float*)d_out;

    cudaFuncSetAttribute(nca_step, cudaFuncAttributeMaxDynamicSharedMemorySize,
                         SMEM_BYTES);

    nca_pack<<<(NPACK + 255) / 256, 256>>>(wp, w1, b1, b2, w3);
    nca_pack_w2frag<<<16, 256>>>(w2);

    for (int s = 0; s < NSTEPS; s++) {
        int ssel = (s == 0) ? 0 : (((s - 1) & 1) ? 2 : 1);
        int dsel = (s == NSTEPS - 1) ? 3 : ((s & 1) ? 2 : 1);
        nca_step<<<NBLK, NTHR, SMEM_BYTES>>>(x, out, ssel, dsel);
    }
}